// round 4
// baseline (speedup 1.0000x reference)
#include <cuda_runtime.h>
#include <cstdint>

// HashEmbedder: Instant-NGP multiresolution hash grid encoding.
// R4 (= R3 re-bench after infra failure, + __stcg output stores):
//  - atomic-free scatter (rank captured during count)
//  - divides -> exact multiplies (res/2 exactly representable)
//  - __float2int_rd
//  - L2-bypass (evict-first) output stores: output is write-once, keep L2
//    for the fine-level table gathers.

#define MAXPTS    524288
#define NBINS_DIM 32
#define NBINS     (NBINS_DIM * NBINS_DIM * NBINS_DIM)   // 32768 = 2^15
#define N_LEVELS  16
#define TABLE_SZ  (1u << 19)
#define TMASK     (TABLE_SZ - 1u)

// scratch (allocations forbidden)
__device__ unsigned g_count[NBINS];
__device__ unsigned g_offset[NBINS];
__device__ unsigned g_binrank[MAXPTS];  // bin (15b) | rank<<15
__device__ float4   g_sorted[MAXPTS];   // xyz + original index (int bits)

// res/2 = 0.5*floor(16*cbrt(2)^i): all exactly representable in fp32
__device__ __constant__ float c_resh[N_LEVELS] = {
    8.f, 10.f, 12.5f, 16.f, 20.f, 25.f, 32.f, 40.f,
    50.5f, 64.f, 80.5f, 101.5f, 128.f, 161.f, 203.f, 256.f
};

__device__ __forceinline__ unsigned part1by2(unsigned x) {
    x &= 0x3FF;
    x = (x | (x << 16)) & 0x030000FF;
    x = (x | (x << 8))  & 0x0300F00F;
    x = (x | (x << 4))  & 0x030C30C3;
    x = (x | (x << 2))  & 0x09249249;
    return x;
}

__device__ __forceinline__ unsigned bin_of(float x, float y, float z) {
    int cx = (int)((x + 1.0f) * 16.0f);
    int cy = (int)((y + 1.0f) * 16.0f);
    int cz = (int)((z + 1.0f) * 16.0f);
    cx = min(max(cx, 0), 31);
    cy = min(max(cy, 0), 31);
    cz = min(max(cz, 0), 31);
    return part1by2((unsigned)cx) | (part1by2((unsigned)cy) << 1) |
           (part1by2((unsigned)cz) << 2);
}

__global__ void zero_bins_kernel() {
    int i = blockIdx.x * blockDim.x + threadIdx.x;
    if (i < NBINS) g_count[i] = 0;
}

// histogram + capture per-point rank from the atomic's return value
__global__ void count_kernel(const float* __restrict__ pts, int n) {
    int i = blockIdx.x * blockDim.x + threadIdx.x;
    if (i >= n) return;
    float x = pts[3 * i + 0], y = pts[3 * i + 1], z = pts[3 * i + 2];
    unsigned b = bin_of(x, y, z);
    unsigned rank = atomicAdd(&g_count[b], 1u);
    g_binrank[i] = b | (rank << 15);
}

// single-block exclusive scan over 32768 bins (1024 threads x 32 each)
__global__ __launch_bounds__(1024)
void scan_kernel() {
    __shared__ unsigned sh[1024];
    int t = threadIdx.x;
    unsigned v[32];
    unsigned s = 0;
#pragma unroll
    for (int i = 0; i < 32; i++) { v[i] = g_count[t * 32 + i]; s += v[i]; }
    sh[t] = s;
    __syncthreads();
    for (int d = 1; d < 1024; d <<= 1) {
        unsigned x = (t >= d) ? sh[t - d] : 0u;
        __syncthreads();
        sh[t] += x;
        __syncthreads();
    }
    unsigned run = sh[t] - s;
#pragma unroll
    for (int i = 0; i < 32; i++) { g_offset[t * 32 + i] = run; run += v[i]; }
}

// atomic-free scatter: pos = offset[bin] + rank
__global__ void scatter_kernel(const float* __restrict__ pts, int n) {
    int i = blockIdx.x * blockDim.x + threadIdx.x;
    if (i >= n) return;
    unsigned br = g_binrank[i];
    unsigned pos = g_offset[br & 0x7FFFu] + (br >> 15);
    float x = pts[3 * i + 0], y = pts[3 * i + 1], z = pts[3 * i + 2];
    g_sorted[pos] = make_float4(x, y, z, __int_as_float(i));
}

__device__ __forceinline__ float2 lerp2(float2 a, float2 b, float t) {
    float2 r;
    r.x = a.x + t * (b.x - a.x);
    r.y = a.y + t * (b.y - a.y);
    return r;
}

__global__ __launch_bounds__(256)
void hashgrid_kernel(const float2* __restrict__ tables,
                     float4* __restrict__ out,   // [n, 8] float4
                     int n)
{
    int s = blockIdx.x * blockDim.x + threadIdx.x;
    if (s >= n) return;

    float4 f = g_sorted[s];
    int orig = __float_as_int(f.w);

    float ax = f.x + 1.0f;
    float ay = f.y + 1.0f;
    float az = f.z + 1.0f;

    const unsigned P0 = 73856093u, P1 = 19349663u, P2 = 83492791u;

    float4* o = out + (size_t)orig * (N_LEVELS / 2);

#pragma unroll
    for (int lp = 0; lp < N_LEVELS / 2; lp++) {
        float4 acc;
#pragma unroll
        for (int h = 0; h < 2; h++) {
            int l = 2 * lp + h;
            // scaled = (p+1) * (res/2); res/2 exact -> <=1ulp vs reference's
            // division by rounded 2/res; floor flips only where w ~ 0/1 where
            // the interpolation is continuous.
            float rh = c_resh[l];
            float sx = ax * rh;
            float sy = ay * rh;
            float sz = az * rh;

            int ixi = __float2int_rd(sx);
            int iyi = __float2int_rd(sy);
            int izi = __float2int_rd(sz);
            float wx = sx - (float)ixi;
            float wy = sy - (float)iyi;
            float wz = sz - (float)izi;

            unsigned hx0 = (unsigned)ixi * P0, hx1 = hx0 + P0;
            unsigned hy0 = (unsigned)iyi * P1, hy1 = hy0 + P1;
            unsigned hz0 = (unsigned)izi * P2, hz1 = hz0 + P2;

            const float2* t = tables + (size_t)l * TABLE_SZ;

            float2 c000 = __ldg(t + ((hx0 ^ hy0 ^ hz0) & TMASK));
            float2 c001 = __ldg(t + ((hx0 ^ hy0 ^ hz1) & TMASK));
            float2 c010 = __ldg(t + ((hx0 ^ hy1 ^ hz0) & TMASK));
            float2 c011 = __ldg(t + ((hx0 ^ hy1 ^ hz1) & TMASK));
            float2 c100 = __ldg(t + ((hx1 ^ hy0 ^ hz0) & TMASK));
            float2 c101 = __ldg(t + ((hx1 ^ hy0 ^ hz1) & TMASK));
            float2 c110 = __ldg(t + ((hx1 ^ hy1 ^ hz0) & TMASK));
            float2 c111 = __ldg(t + ((hx1 ^ hy1 ^ hz1) & TMASK));

            float2 c00 = lerp2(c000, c001, wz);
            float2 c01 = lerp2(c010, c011, wz);
            float2 c10 = lerp2(c100, c101, wz);
            float2 c11 = lerp2(c110, c111, wz);
            float2 c0  = lerp2(c00, c01, wy);
            float2 c1  = lerp2(c10, c11, wy);
            float2 r   = lerp2(c0, c1, wx);

            if (h == 0) { acc.x = r.x; acc.y = r.y; }
            else        { acc.z = r.x; acc.w = r.y; }
        }
        __stcg(o + lp, acc);   // write-once output: don't pollute L2
    }
}

extern "C" void kernel_launch(void* const* d_in, const int* in_sizes, int n_in,
                              void* d_out, int out_size)
{
    const float*  pts    = (const float*)d_in[0];   // [n, 3]
    const float2* tables = (const float2*)d_in[1];  // [16, 2^19] float2
    float4*       out    = (float4*)d_out;          // [n, 8] float4

    int n = in_sizes[0] / 3;
    if (n > MAXPTS) n = MAXPTS;

    int T = 256;
    int gp = (n + T - 1) / T;

    zero_bins_kernel<<<(NBINS + T - 1) / T, T>>>();
    count_kernel<<<gp, T>>>(pts, n);
    scan_kernel<<<1, 1024>>>();
    scatter_kernel<<<gp, T>>>(pts, n);
    hashgrid_kernel<<<gp, T>>>(tables, out, n);
}

// round 6
// speedup vs baseline: 1.1167x; 1.1167x over previous
#include <cuda_runtime.h>
#include <cstdint>

// HashEmbedder: Instant-NGP multiresolution hash grid encoding.
// R6 = R5 re-bench after infra failure (no changes):
// explicit 2-stage software pipeline across levels (issue level l+1's
// 8 gathers before consuming level l), reg cap raised to 64 via
// __launch_bounds__(256,4). __stcg reverted.
// Keeps: Morton sort, atomic-free scatter, exact multiplies, float2int_rd.

#define MAXPTS    524288
#define NBINS_DIM 32
#define NBINS     (NBINS_DIM * NBINS_DIM * NBINS_DIM)   // 32768 = 2^15
#define N_LEVELS  16
#define TABLE_SZ  (1u << 19)
#define TMASK     (TABLE_SZ - 1u)

// scratch (allocations forbidden)
__device__ unsigned g_count[NBINS];
__device__ unsigned g_offset[NBINS];
__device__ unsigned g_binrank[MAXPTS];  // bin (15b) | rank<<15
__device__ float4   g_sorted[MAXPTS];   // xyz + original index (int bits)

// res/2 = 0.5*floor(16*cbrt(2)^i): all exactly representable in fp32
__device__ __constant__ float c_resh[N_LEVELS] = {
    8.f, 10.f, 12.5f, 16.f, 20.f, 25.f, 32.f, 40.f,
    50.5f, 64.f, 80.5f, 101.5f, 128.f, 161.f, 203.f, 256.f
};

__device__ __forceinline__ unsigned part1by2(unsigned x) {
    x &= 0x3FF;
    x = (x | (x << 16)) & 0x030000FF;
    x = (x | (x << 8))  & 0x0300F00F;
    x = (x | (x << 4))  & 0x030C30C3;
    x = (x | (x << 2))  & 0x09249249;
    return x;
}

__device__ __forceinline__ unsigned bin_of(float x, float y, float z) {
    int cx = (int)((x + 1.0f) * 16.0f);
    int cy = (int)((y + 1.0f) * 16.0f);
    int cz = (int)((z + 1.0f) * 16.0f);
    cx = min(max(cx, 0), 31);
    cy = min(max(cy, 0), 31);
    cz = min(max(cz, 0), 31);
    return part1by2((unsigned)cx) | (part1by2((unsigned)cy) << 1) |
           (part1by2((unsigned)cz) << 2);
}

__global__ void zero_bins_kernel() {
    int i = blockIdx.x * blockDim.x + threadIdx.x;
    if (i < NBINS) g_count[i] = 0;
}

__global__ void count_kernel(const float* __restrict__ pts, int n) {
    int i = blockIdx.x * blockDim.x + threadIdx.x;
    if (i >= n) return;
    float x = pts[3 * i + 0], y = pts[3 * i + 1], z = pts[3 * i + 2];
    unsigned b = bin_of(x, y, z);
    unsigned rank = atomicAdd(&g_count[b], 1u);
    g_binrank[i] = b | (rank << 15);
}

// single-block exclusive scan over 32768 bins (1024 threads x 32 each)
__global__ __launch_bounds__(1024)
void scan_kernel() {
    __shared__ unsigned sh[1024];
    int t = threadIdx.x;
    unsigned v[32];
    unsigned s = 0;
#pragma unroll
    for (int i = 0; i < 32; i++) { v[i] = g_count[t * 32 + i]; s += v[i]; }
    sh[t] = s;
    __syncthreads();
    for (int d = 1; d < 1024; d <<= 1) {
        unsigned x = (t >= d) ? sh[t - d] : 0u;
        __syncthreads();
        sh[t] += x;
        __syncthreads();
    }
    unsigned run = sh[t] - s;
#pragma unroll
    for (int i = 0; i < 32; i++) { g_offset[t * 32 + i] = run; run += v[i]; }
}

// atomic-free scatter: pos = offset[bin] + rank
__global__ void scatter_kernel(const float* __restrict__ pts, int n) {
    int i = blockIdx.x * blockDim.x + threadIdx.x;
    if (i >= n) return;
    unsigned br = g_binrank[i];
    unsigned pos = g_offset[br & 0x7FFFu] + (br >> 15);
    float x = pts[3 * i + 0], y = pts[3 * i + 1], z = pts[3 * i + 2];
    g_sorted[pos] = make_float4(x, y, z, __int_as_float(i));
}

__device__ __forceinline__ float2 lerp2(float2 a, float2 b, float t) {
    float2 r;
    r.x = a.x + t * (b.x - a.x);
    r.y = a.y + t * (b.y - a.y);
    return r;
}

// issue the 8 corner gathers + weights for level `lv` into buffer `buf`
#define LOAD_LEVEL(lv, buf)                                                  \
    do {                                                                     \
        float rh = c_resh[lv];                                               \
        float sx = ax * rh, sy = ay * rh, sz = az * rh;                      \
        int ixi = __float2int_rd(sx);                                        \
        int iyi = __float2int_rd(sy);                                        \
        int izi = __float2int_rd(sz);                                        \
        wbx[buf] = sx - (float)ixi;                                          \
        wby[buf] = sy - (float)iyi;                                          \
        wbz[buf] = sz - (float)izi;                                          \
        unsigned hx0 = (unsigned)ixi * P0, hx1 = hx0 + P0;                   \
        unsigned hy0 = (unsigned)iyi * P1, hy1 = hy0 + P1;                   \
        unsigned hz0 = (unsigned)izi * P2, hz1 = hz0 + P2;                   \
        const float2* t = tables + (size_t)(lv) * TABLE_SZ;                  \
        cbuf[buf][0] = __ldg(t + ((hx0 ^ hy0 ^ hz0) & TMASK));               \
        cbuf[buf][1] = __ldg(t + ((hx0 ^ hy0 ^ hz1) & TMASK));               \
        cbuf[buf][2] = __ldg(t + ((hx0 ^ hy1 ^ hz0) & TMASK));               \
        cbuf[buf][3] = __ldg(t + ((hx0 ^ hy1 ^ hz1) & TMASK));               \
        cbuf[buf][4] = __ldg(t + ((hx1 ^ hy0 ^ hz0) & TMASK));               \
        cbuf[buf][5] = __ldg(t + ((hx1 ^ hy0 ^ hz1) & TMASK));               \
        cbuf[buf][6] = __ldg(t + ((hx1 ^ hy1 ^ hz0) & TMASK));               \
        cbuf[buf][7] = __ldg(t + ((hx1 ^ hy1 ^ hz1) & TMASK));               \
    } while (0)

__global__ __launch_bounds__(256, 4)
void hashgrid_kernel(const float2* __restrict__ tables,
                     float4* __restrict__ out,   // [n, 8] float4
                     int n)
{
    int s = blockIdx.x * blockDim.x + threadIdx.x;
    if (s >= n) return;

    float4 f = g_sorted[s];
    int orig = __float_as_int(f.w);

    float ax = f.x + 1.0f;
    float ay = f.y + 1.0f;
    float az = f.z + 1.0f;

    const unsigned P0 = 73856093u, P1 = 19349663u, P2 = 83492791u;

    float2 cbuf[2][8];
    float wbx[2], wby[2], wbz[2];

    // prologue: level 0 in flight
    LOAD_LEVEL(0, 0);

    float4* o = out + (size_t)orig * (N_LEVELS / 2);
    float4 acc;

#pragma unroll
    for (int l = 0; l < N_LEVELS; l++) {
        const int cur = l & 1;
        const int nxt = cur ^ 1;

        // issue next level's gathers BEFORE consuming this level's corners
        if (l + 1 < N_LEVELS) LOAD_LEVEL(l + 1, nxt);

        float wx = wbx[cur], wy = wby[cur], wz = wbz[cur];
        float2 c00 = lerp2(cbuf[cur][0], cbuf[cur][1], wz);
        float2 c01 = lerp2(cbuf[cur][2], cbuf[cur][3], wz);
        float2 c10 = lerp2(cbuf[cur][4], cbuf[cur][5], wz);
        float2 c11 = lerp2(cbuf[cur][6], cbuf[cur][7], wz);
        float2 c0  = lerp2(c00, c01, wy);
        float2 c1  = lerp2(c10, c11, wy);
        float2 r   = lerp2(c0, c1, wx);

        if ((l & 1) == 0) {
            acc.x = r.x; acc.y = r.y;
        } else {
            acc.z = r.x; acc.w = r.y;
            o[l >> 1] = acc;
        }
    }
}

extern "C" void kernel_launch(void* const* d_in, const int* in_sizes, int n_in,
                              void* d_out, int out_size)
{
    const float*  pts    = (const float*)d_in[0];   // [n, 3]
    const float2* tables = (const float2*)d_in[1];  // [16, 2^19] float2
    float4*       out    = (float4*)d_out;          // [n, 8] float4

    int n = in_sizes[0] / 3;
    if (n > MAXPTS) n = MAXPTS;

    int T = 256;
    int gp = (n + T - 1) / T;

    zero_bins_kernel<<<(NBINS + T - 1) / T, T>>>();
    count_kernel<<<gp, T>>>(pts, n);
    scan_kernel<<<1, 1024>>>();
    scatter_kernel<<<gp, T>>>(pts, n);
    hashgrid_kernel<<<gp, T>>>(tables, out, n);
}